// round 4
// baseline (speedup 1.0000x reference)
#include <cuda_runtime.h>
#include <cstdint>

// Problem constants (fixed by reference)
#define NN   100000
#define EE   1600000
#define FH   128      // F_IN == H == HG
#define H3   384      // 3*HG
#define CC   40
#define LL   3

// ---------------- scratch (device globals; no allocation allowed) ----------
__device__ float g_xh[(size_t)NN * FH];
__device__ float g_xw[(size_t)NN * FH];
__device__ float g_h [(size_t)NN * FH];
__device__ float g_gi[(size_t)NN * H3];   // also reused as agg buffer (first NN*FH)
__device__ float g_gh[(size_t)NN * H3];
__device__ float g_deg [NN];
__device__ float g_dinv[NN];

// ---------------- degree / normalization ----------------
__global__ void init_deg_kernel() {
    int i = blockIdx.x * blockDim.x + threadIdx.x;
    if (i < NN) g_deg[i] = 1.0f;   // self-loop weight 1
}

__global__ void accum_deg_kernel(const int* __restrict__ dst,
                                 const float* __restrict__ ew) {
    int e = blockIdx.x * blockDim.x + threadIdx.x;
    if (e < EE) atomicAdd(&g_deg[dst[e]], ew[e]);
}

__global__ void dinv_kernel() {
    int i = blockIdx.x * blockDim.x + threadIdx.x;
    if (i < NN) g_dinv[i] = rsqrtf(g_deg[i]);   // deg >= 1 always
}

// =====================================================================
// TF32 tensor-core GEMM v2: C[M,Ncols] = A[M,128] * B (+bias)(+relu)
//   TRANSB=false: B is [128, Ncols] row-major
//   TRANSB=true : B is [Ncols, 128] row-major (C = A * B^T)
//   SELF=true  : additionally write agg[r] = C[r]*dinv[r]^2 (Ncols==128 only)
// CTA tile 128x128, K=128 fully resident in smem as PRE-SWIZZLED MMA
// fragments. 512 threads / 16 warps, warp tile 32x32, mma.m16n8k8.tf32.
//   AsF: float4[128*32]  (tm in 0..7, ks in 0..15, lane)   64KB
//   BsF: float2[256*32]  (tn in 0..15, ks in 0..15, lane)  64KB
// =====================================================================
#define GEMM_SMEM_BYTES (128 * 1024)

__device__ __forceinline__ float to_tf32(float v) {
    uint32_t o;
    asm volatile("cvt.rna.tf32.f32 %0, %1;" : "=r"(o) : "f"(v));
    return __uint_as_float(o);
}

__device__ __forceinline__ void mma_tf32(float* d, const float4& a,
                                         const float2& b) {
    asm volatile(
        "mma.sync.aligned.m16n8k8.row.col.f32.tf32.tf32.f32 "
        "{%0,%1,%2,%3}, {%4,%5,%6,%7}, {%8,%9}, {%0,%1,%2,%3};\n"
        : "+f"(d[0]), "+f"(d[1]), "+f"(d[2]), "+f"(d[3])
        : "r"(__float_as_uint(a.x)), "r"(__float_as_uint(a.y)),
          "r"(__float_as_uint(a.z)), "r"(__float_as_uint(a.w)),
          "r"(__float_as_uint(b.x)), "r"(__float_as_uint(b.y)));
}

template<bool TRANSB, bool BIAS, bool RELU, bool SELF>
__global__ __launch_bounds__(512, 1)
void gemm_tf32_kernel(const float* __restrict__ A,
                      const float* __restrict__ B,
                      const float* __restrict__ bias,
                      float* __restrict__ C,
                      float* __restrict__ agg,
                      int M, int Ncols) {
    extern __shared__ float4 smem4[];
    float4* AsF = smem4;                       // [128*32] float4
    float2* BsF = (float2*)(smem4 + 128 * 32); // [256*32] float2

    const int tid  = threadIdx.x;
    const int lane = tid & 31;
    const int wid  = tid >> 5;                 // 0..15
    const int lr   = lane >> 2;                // 0..7
    const int lc   = lane & 3;                 // 0..3
    const int bm = blockIdx.y * 128;
    const int bn = blockIdx.x * 128;

    // ---- fill A fragments: 128 (tm,ks) tasks over 16 warps ----
    #pragma unroll
    for (int it = 0; it < 8; it++) {
        int task = it * 16 + wid;
        int tm = task >> 4;        // 0..7
        int ks = task & 15;        // 0..15
        int r0 = bm + tm * 16 + lr;
        int r1 = r0 + 8;
        int k0 = ks * 8 + lc;
        float a0 = 0.f, a1 = 0.f, a2 = 0.f, a3 = 0.f;
        if (r0 < M) {
            a0 = A[(size_t)r0 * 128 + k0];
            a2 = A[(size_t)r0 * 128 + k0 + 4];
        }
        if (r1 < M) {
            a1 = A[(size_t)r1 * 128 + k0];
            a3 = A[(size_t)r1 * 128 + k0 + 4];
        }
        AsF[task * 32 + lane] = make_float4(to_tf32(a0), to_tf32(a1),
                                            to_tf32(a2), to_tf32(a3));
    }
    // ---- fill B fragments: 256 (tn,ks) tasks over 16 warps ----
    #pragma unroll
    for (int it = 0; it < 16; it++) {
        int task = it * 16 + wid;
        int tn = task >> 4;        // 0..15
        int ks = task & 15;
        int n  = bn + tn * 8 + lr;
        int k0 = ks * 8 + lc;
        float b0, b1;
        if (TRANSB) {              // B [Ncols,128] row-major, B^T used
            b0 = B[(size_t)n * 128 + k0];
            b1 = B[(size_t)n * 128 + k0 + 4];
        } else {                   // B [128,Ncols] row-major
            b0 = B[(size_t)k0 * Ncols + n];
            b1 = B[(size_t)(k0 + 4) * Ncols + n];
        }
        BsF[task * 32 + lane] = make_float2(to_tf32(b0), to_tf32(b1));
    }
    __syncthreads();

    // warp tile: 32 rows x 32 cols; warp grid 4x4
    const int wtm = wid & 3;       // m-warp 0..3
    const int wtn = wid >> 2;      // n-warp 0..3

    float acc[2][4][4];
    #pragma unroll
    for (int mi = 0; mi < 2; mi++)
        #pragma unroll
        for (int ni = 0; ni < 4; ni++)
            #pragma unroll
            for (int j = 0; j < 4; j++) acc[mi][ni][j] = 0.f;

    const float4* ap0 = AsF + ((wtm * 2 + 0) * 16) * 32 + lane;
    const float4* ap1 = AsF + ((wtm * 2 + 1) * 16) * 32 + lane;
    const float2* bp0 = BsF + ((wtn * 4 + 0) * 16) * 32 + lane;
    const float2* bp1 = BsF + ((wtn * 4 + 1) * 16) * 32 + lane;
    const float2* bp2 = BsF + ((wtn * 4 + 2) * 16) * 32 + lane;
    const float2* bp3 = BsF + ((wtn * 4 + 3) * 16) * 32 + lane;

    #pragma unroll
    for (int ks = 0; ks < 16; ks++) {
        float4 a0 = ap0[ks * 32];
        float4 a1 = ap1[ks * 32];
        float2 b0 = bp0[ks * 32];
        float2 b1 = bp1[ks * 32];
        float2 b2 = bp2[ks * 32];
        float2 b3 = bp3[ks * 32];
        mma_tf32(acc[0][0], a0, b0); mma_tf32(acc[0][1], a0, b1);
        mma_tf32(acc[0][2], a0, b2); mma_tf32(acc[0][3], a0, b3);
        mma_tf32(acc[1][0], a1, b0); mma_tf32(acc[1][1], a1, b1);
        mma_tf32(acc[1][2], a1, b2); mma_tf32(acc[1][3], a1, b3);
    }

    // ---- epilogue ----
    #pragma unroll
    for (int mi = 0; mi < 2; mi++) {
        int r0 = bm + wtm * 32 + mi * 16 + lr;
        int r1 = r0 + 8;
        float di0 = 0.f, di1 = 0.f;
        if (SELF) {
            if (r0 < M) di0 = g_dinv[r0];
            if (r1 < M) di1 = g_dinv[r1];
        }
        #pragma unroll
        for (int ni = 0; ni < 4; ni++) {
            int c0 = bn + wtn * 32 + ni * 8 + (lc << 1);
            float b0 = 0.f, b1 = 0.f;
            if (BIAS) { b0 = bias[c0]; b1 = bias[c0 + 1]; }
            float v0 = acc[mi][ni][0] + b0;
            float v1 = acc[mi][ni][1] + b1;
            float v2 = acc[mi][ni][2] + b0;
            float v3 = acc[mi][ni][3] + b1;
            if (RELU) {
                v0 = fmaxf(v0, 0.f); v1 = fmaxf(v1, 0.f);
                v2 = fmaxf(v2, 0.f); v3 = fmaxf(v3, 0.f);
            }
            if (r0 < M) {
                *(float2*)(C + (size_t)r0 * Ncols + c0) = make_float2(v0, v1);
                if (SELF)
                    *(float2*)(agg + (size_t)r0 * 128 + c0) =
                        make_float2(v0 * di0 * di0, v1 * di0 * di0);
            }
            if (r1 < M) {
                *(float2*)(C + (size_t)r1 * Ncols + c0) = make_float2(v2, v3);
                if (SELF)
                    *(float2*)(agg + (size_t)r1 * 128 + c0) =
                        make_float2(v2 * di1 * di1, v3 * di1 * di1);
            }
        }
    }
}

// ---------------- fp32 fallback GEMM (used for fc, Ncols=40) --------------
__global__ void gemm_fc_kernel(const float* __restrict__ A,
                               const float* __restrict__ B,
                               const float* __restrict__ bias,
                               float* __restrict__ C,
                               int M, int Ncols) {
    constexpr int K  = 128;
    constexpr int BM = 64, BN = 64, BK = 16;
    __shared__ float As[BK][BM + 4];
    __shared__ float Bs[BK][BN + 4];

    const int tid = threadIdx.x;
    const int bm = blockIdx.y * BM;
    const int bn = blockIdx.x * BN;
    const int tx = tid & 15;
    const int ty = tid >> 4;

    float acc[4][4] = {};

    for (int k0 = 0; k0 < K; k0 += BK) {
        {
            const int arow = tid >> 2;
            const int acol = (tid & 3) << 2;
            float4 av = make_float4(0.f, 0.f, 0.f, 0.f);
            const int gr = bm + arow;
            if (gr < M)
                av = *(const float4*)(A + (size_t)gr * K + k0 + acol);
            As[acol + 0][arow] = av.x;
            As[acol + 1][arow] = av.y;
            As[acol + 2][arow] = av.z;
            As[acol + 3][arow] = av.w;
        }
        {
            const int brow = tid >> 4;
            const int bcol = (tid & 15) << 2;
            const int gc = bn + bcol;
            Bs[brow][bcol + 0] = (gc + 0 < Ncols) ? B[(size_t)(k0 + brow) * Ncols + gc + 0] : 0.f;
            Bs[brow][bcol + 1] = (gc + 1 < Ncols) ? B[(size_t)(k0 + brow) * Ncols + gc + 1] : 0.f;
            Bs[brow][bcol + 2] = (gc + 2 < Ncols) ? B[(size_t)(k0 + brow) * Ncols + gc + 2] : 0.f;
            Bs[brow][bcol + 3] = (gc + 3 < Ncols) ? B[(size_t)(k0 + brow) * Ncols + gc + 3] : 0.f;
        }
        __syncthreads();

        #pragma unroll
        for (int k = 0; k < BK; k++) {
            float4 a = *(const float4*)(&As[k][ty << 2]);
            float4 b = *(const float4*)(&Bs[k][tx << 2]);
            acc[0][0] += a.x * b.x; acc[0][1] += a.x * b.y;
            acc[0][2] += a.x * b.z; acc[0][3] += a.x * b.w;
            acc[1][0] += a.y * b.x; acc[1][1] += a.y * b.y;
            acc[1][2] += a.y * b.z; acc[1][3] += a.y * b.w;
            acc[2][0] += a.z * b.x; acc[2][1] += a.z * b.y;
            acc[2][2] += a.z * b.z; acc[2][3] += a.z * b.w;
            acc[3][0] += a.w * b.x; acc[3][1] += a.w * b.y;
            acc[3][2] += a.w * b.z; acc[3][3] += a.w * b.w;
        }
        __syncthreads();
    }

    float bv[4] = {0.f, 0.f, 0.f, 0.f};
    #pragma unroll
    for (int j = 0; j < 4; j++) {
        int c = bn + (tx << 2) + j;
        bv[j] = (c < Ncols) ? bias[c] : 0.f;
    }
    #pragma unroll
    for (int i = 0; i < 4; i++) {
        int r = bm + (ty << 2) + i;
        if (r >= M) continue;
        #pragma unroll
        for (int j = 0; j < 4; j++) {
            int c = bn + (tx << 2) + j;
            if (c >= Ncols) continue;
            C[(size_t)r * Ncols + c] = acc[i][j] + bv[j];
        }
    }
}

// ---------------- edge scatter: one warp per edge ----------------
__global__ void scatter_kernel(const int* __restrict__ src,
                               const int* __restrict__ dst,
                               const float* __restrict__ ew,
                               const float* __restrict__ xw,
                               float* __restrict__ agg) {
    int warp = (blockIdx.x * blockDim.x + threadIdx.x) >> 5;
    int lane = threadIdx.x & 31;
    if (warp >= EE) return;
    int s = src[warp];
    int d = dst[warp];
    float norm = g_dinv[s] * ew[warp] * g_dinv[d];
    float4 v = ((const float4*)(xw + (size_t)s * FH))[lane];
    float* base = agg + (size_t)d * FH + (lane << 2);
    atomicAdd(base + 0, v.x * norm);
    atomicAdd(base + 1, v.y * norm);
    atomicAdd(base + 2, v.z * norm);
    atomicAdd(base + 3, v.w * norm);
}

// ---------------- bias + relu: xh = relu(agg + b) ----------------
__global__ void bias_relu_kernel(const float* __restrict__ agg,
                                 float* __restrict__ xh,
                                 const float* __restrict__ b) {
    size_t idx = (size_t)blockIdx.x * blockDim.x + threadIdx.x;
    if (idx >= (size_t)NN * FH) return;
    int f = (int)(idx & (FH - 1));
    xh[idx] = fmaxf(agg[idx] + b[f], 0.f);
}

// ---------------- GRU elementwise ----------------
__global__ void gru_kernel(const float* __restrict__ gi,
                           const float* __restrict__ gh,
                           const float* __restrict__ hprev,
                           float* __restrict__ hout) {
    size_t idx = (size_t)blockIdx.x * blockDim.x + threadIdx.x;
    if (idx >= (size_t)NN * FH) return;
    int n = (int)(idx >> 7);
    int j = (int)(idx & (FH - 1));
    size_t base = (size_t)n * H3 + j;
    float ir = gi[base          ];
    float iz = gi[base + FH     ];
    float in_ = gi[base + 2 * FH];
    float hr = gh[base          ];
    float hz = gh[base + FH     ];
    float hn = gh[base + 2 * FH];
    float hv = hprev[idx];
    float r = 1.f / (1.f + expf(-(ir + hr)));
    float z = 1.f / (1.f + expf(-(iz + hz)));
    float nn = tanhf(in_ + r * hn);
    hout[idx] = (1.f - z) * nn + z * hv;
}

// ---------------- host orchestration ----------------
typedef void (*gemm_fn_t)(const float*, const float*, const float*, float*,
                          float*, int, int);

extern "C" void kernel_launch(void* const* d_in, const int* in_sizes, int n_in,
                              void* d_out, int out_size) {
    const float* x     = (const float*)d_in[0];
    const int*   ei    = (const int*)  d_in[1];
    const float* ew    = (const float*)d_in[2];
    const float* h0    = (const float*)d_in[3];
    const float* linW  = (const float*)d_in[4];
    const float* linB  = (const float*)d_in[5];
    const float* convW = (const float*)d_in[6];
    const float* convB = (const float*)d_in[7];
    const float* Wih   = (const float*)d_in[8];
    const float* Whh   = (const float*)d_in[9];
    const float* bih   = (const float*)d_in[10];
    const float* bhh   = (const float*)d_in[11];
    const float* fcW   = (const float*)d_in[12];
    const float* fcB   = (const float*)d_in[13];
    float* out = (float*)d_out;

    const int* src = ei;
    const int* dst = ei + EE;

    // one-time: allow >48KB dynamic smem for tf32 instantiations
    static bool s_attr_done = false;
    if (!s_attr_done) {
        cudaFuncSetAttribute(gemm_tf32_kernel<false, true, true, false>,
                             cudaFuncAttributeMaxDynamicSharedMemorySize, GEMM_SMEM_BYTES);
        cudaFuncSetAttribute(gemm_tf32_kernel<true, true, false, false>,
                             cudaFuncAttributeMaxDynamicSharedMemorySize, GEMM_SMEM_BYTES);
        cudaFuncSetAttribute(gemm_tf32_kernel<false, false, false, true>,
                             cudaFuncAttributeMaxDynamicSharedMemorySize, GEMM_SMEM_BYTES);
        s_attr_done = true;
    }

    // scratch symbol addresses (not stream ops; graph-capture safe)
    float *p_xh, *p_xw, *p_h, *p_gi, *p_gh;
    cudaGetSymbolAddress((void**)&p_xh, g_xh);
    cudaGetSymbolAddress((void**)&p_xw, g_xw);
    cudaGetSymbolAddress((void**)&p_h,  g_h);
    cudaGetSymbolAddress((void**)&p_gi, g_gi);
    cudaGetSymbolAddress((void**)&p_gh, g_gh);
    float* p_agg = p_gi;   // reuse gi's first NN*FH floats as agg scratch

    const size_t NF = (size_t)NN * FH;
    const int EB = 256;

    const dim3 blk512(512);
    const dim3 grid128(1, (NN + 127) / 128);     // Ncols=128
    const dim3 grid384(3, (NN + 127) / 128);     // Ncols=384
    const size_t sm = GEMM_SMEM_BYTES;

    // degree + normalization
    init_deg_kernel<<<(NN + 255) / 256, 256>>>();
    accum_deg_kernel<<<(EE + EB - 1) / EB, EB>>>(dst, ew);
    dinv_kernel<<<(NN + 255) / 256, 256>>>();

    // xh = relu(x @ linW + linB)
    gemm_tf32_kernel<false, true, true, false><<<grid128, blk512, sm>>>(
        x, linW, linB, p_xh, nullptr, NN, FH);

    // h = GRU(xh, h0)
    gemm_tf32_kernel<true, true, false, false><<<grid384, blk512, sm>>>(
        p_xh, Wih, bih, p_gi, nullptr, NN, H3);
    gemm_tf32_kernel<true, true, false, false><<<grid384, blk512, sm>>>(
        h0, Whh, bhh, p_gh, nullptr, NN, H3);
    gru_kernel<<<(int)((NF + 255) / 256), 256>>>(p_gi, p_gh, h0, p_h);

    for (int l = 0; l < LL; l++) {
        const float* W = convW + (size_t)l * FH * FH;
        const float* b = convB + (size_t)l * FH;
        // xw = xh @ W ; agg = xw * dinv^2 (fused self-loop init)
        gemm_tf32_kernel<false, false, false, true><<<grid128, blk512, sm>>>(
            p_xh, W, nullptr, p_xw, p_agg, NN, FH);
        // edge scatter into agg
        scatter_kernel<<<(EE * 32 + 255) / 256, 256>>>(src, dst, ew, p_xw, p_agg);
        // xh = relu(agg + b)
        bias_relu_kernel<<<(int)((NF + 255) / 256), 256>>>(p_agg, p_xh, b);
        // h = GRU(xh, h)   (gi may be overwritten now; agg no longer needed)
        gemm_tf32_kernel<true, true, false, false><<<grid384, blk512, sm>>>(
            p_xh, Wih, bih, p_gi, nullptr, NN, H3);
        gemm_tf32_kernel<true, true, false, false><<<grid384, blk512, sm>>>(
            p_h, Whh, bhh, p_gh, nullptr, NN, H3);
        gru_kernel<<<(int)((NF + 255) / 256), 256>>>(p_gi, p_gh, p_h, p_h);
    }

    // out = h @ fcW + fcB (fp32 fallback: Ncols=40)
    {
        dim3 grid((CC + 63) / 64, (NN + 63) / 64);
        gemm_fc_kernel<<<grid, 256>>>(p_h, fcW, fcB, out, NN, CC);
    }
}